// round 6
// baseline (speedup 1.0000x reference)
#include <cuda_runtime.h>
#include <math.h>
#include <stdint.h>

// ---------------- problem constants ----------------
#define NB   2048
#define SQN  64
#define PCN  24
#define FDIM 16
#define HDIM 128
#define DDIM 256
#define TDIM 128
#define ADIM 4672
#define E_ADJ 420
#define E_OCC 24
#define E_ATT 40
#define E_DEF 40
#define E_REV 24

// ---------------- scratch (static device globals: allocation-free) ----------------
__device__ float g_shared[NB * DDIM];  // 2 MB
__device__ float g_pt[NB * TDIM];      // 1 MB
__device__ float g_vt[NB * TDIM];      // 1 MB

// gelu(x) = x * sigmoid(2u), u = 0.79788456*(x + 0.044715 x^3)
// tanh computed via __expf (MUFU.EX2), rel err ~1e-6 — far under 1e-3 budget.
__device__ __forceinline__ float gelu_f(float x) {
    float u = 0.7978845608028654f * x + 0.0356774081f * x * x * x;
    float au = fabsf(u);
    float e = __expf(-2.0f * au);
    float t = __fdividef(1.0f - e, 1.0f + e);
    t = copysignf(t, u);
    return 0.5f * x * (1.0f + t);
}

// packed f32x2 FMA: d = a*b + d  (FFMA2 — ptxas won't auto-fuse; PTX-only)
__device__ __forceinline__ void ffma2(uint64_t& d, uint64_t a, uint64_t b) {
    asm("fma.rn.f32x2 %0, %1, %2, %0;" : "+l"(d) : "l"(a), "l"(b));
}
__device__ __forceinline__ float pairsum(uint64_t p) {
    float lo, hi;
    asm("mov.b64 {%0, %1}, %2;" : "=f"(lo), "=f"(hi) : "l"(p));
    return lo + hi;
}
__device__ __forceinline__ uint64_t dupf(float a) {
    uint64_t r;
    asm("mov.b64 %0, {%1, %1};" : "=l"(r) : "f"(a));
    return r;
}

// Stage a 128x128 weight tile (row stride rs floats, col offset co) into
// k-pair-interleaved smem layout: dst[kp*256 + c*2 + (k&1)] = W[k][c].
// Conflict-free: STS.128 at word 4*lane; LDG as float2 pairs of rows.
__device__ __forceinline__ void stage_kint(float* __restrict__ dst,
                                           const float* __restrict__ W,
                                           int rs, int co, int t) {
#pragma unroll
    for (int it = 0; it < 16; it++) {
        int m = t + it * 256;            // 64 kp x 64 col-pairs
        int kp = m >> 6;
        int c  = (m & 63) * 2;
        float2 r0 = *(const float2*)&W[(2 * kp)     * rs + co + c];
        float2 r1 = *(const float2*)&W[(2 * kp + 1) * rs + co + c];
        float4 o = make_float4(r0.x, r1.x, r0.y, r1.y);
        *(float4*)&dst[kp * 256 + c * 2] = o;
    }
}

// ---------------- smem layout for board kernel (floats) ----------------
#define OFF_HSQ  0        // 64*128
#define OFF_HPC  8192     // 24*128
#define OFF_RADJ 11264    // 64*128
#define OFF_ROCC 19456    // 64*128
#define OFF_RATT 27648    // 24*128
#define OFF_RDEF 30720    // 24*128
#define OFF_RREV 33792    // 24*128
#define OFF_WST  36864    // 128*128 staging (k-interleaved for GEMM phases)
#define OFF_SACC 53248    // 256
#define OFF_EIDX 53504    // 548 ints
#define SMEM1_BYTES (53504*4 + 548*4)   // 216208 B

// ============================================================================
// Kernel 1: one CTA per board. Fully fused GNN -> g_shared[b][256].
// ============================================================================
__global__ void __launch_bounds__(256, 1) board_kernel(
    const float* __restrict__ x_sq, const float* __restrict__ x_pc,
    const float* __restrict__ W_in_sq, const float* __restrict__ b_in_sq,
    const float* __restrict__ W_in_pc, const float* __restrict__ b_in_pc,
    const float* __restrict__ W_adj, const float* __restrict__ W_occ,
    const float* __restrict__ W_att, const float* __restrict__ W_def,
    const float* __restrict__ W_rev,
    const float* __restrict__ W_out, const float* __restrict__ b_out,
    const int* __restrict__ ei_adj, const int* __restrict__ ei_occ,
    const int* __restrict__ ei_att, const int* __restrict__ ei_def,
    const int* __restrict__ ei_rev)
{
    extern __shared__ float sm[];
    float* h_sq   = sm + OFF_HSQ;
    float* h_pc   = sm + OFF_HPC;
    float* rawAdj = sm + OFF_RADJ;
    float* rawOcc = sm + OFF_ROCC;
    float* rawAtt = sm + OFF_RATT;
    float* rawDef = sm + OFF_RDEF;
    float* rawRev = sm + OFF_RREV;
    float* wst    = sm + OFF_WST;
    float* sacc   = sm + OFF_SACC;
    int*   eidx   = (int*)(sm + OFF_EIDX);

    const int b = blockIdx.x;
    const int t = threadIdx.x;

    // ---- load edges (convert to board-local, pack s | d<<8) ----
    {
        const int ba = b * E_ADJ;
        for (int i = t; i < E_ADJ; i += 256) {
            int s = ei_adj[ba + i] - b * SQN;
            int d = ei_adj[NB * E_ADJ + ba + i] - b * SQN;
            eidx[i] = s | (d << 8);
        }
        const int bo = b * E_OCC;
        for (int i = t; i < E_OCC; i += 256) {
            int s = ei_occ[bo + i] - b * PCN;                  // src: piece
            int d = ei_occ[NB * E_OCC + bo + i] - b * SQN;     // dst: square
            eidx[E_ADJ + i] = s | (d << 8);
        }
        const int bt = b * E_ATT;
        for (int i = t; i < E_ATT; i += 256) {
            int s  = ei_att[bt + i] - b * PCN;
            int d  = ei_att[NB * E_ATT + bt + i] - b * PCN;
            eidx[E_ADJ + E_OCC + i] = s | (d << 8);
            int s2 = ei_def[bt + i] - b * PCN;
            int d2 = ei_def[NB * E_DEF + bt + i] - b * PCN;
            eidx[E_ADJ + E_OCC + E_ATT + i] = s2 | (d2 << 8);
        }
        for (int i = t; i < E_REV; i += 256) {
            int s = ei_rev[bo + i] - b * SQN;                  // src: square
            int d = ei_rev[NB * E_REV + bo + i] - b * PCN;     // dst: piece
            eidx[E_ADJ + E_OCC + E_ATT + E_DEF + i] = s | (d << 8);
        }
    }

    // ---- zero raw buffers (25600 floats) + sacc ----
    {
        float4* r4 = (float4*)rawAdj;
        for (int i = t; i < 6400; i += 256) r4[i] = make_float4(0.f, 0.f, 0.f, 0.f);
        sacc[t & 255] = 0.f;
    }

    // ---- stage x tiles + input weights into wst region (plain layout) ----
    float* xs  = wst;              // 64*16
    float* xp  = wst + 1024;       // 24*16
    float* wi1 = wst + 2048;       // 16*128
    float* wi2 = wst + 4096;       // 16*128
    for (int i = t; i < SQN * FDIM; i += 256) xs[i] = x_sq[b * SQN * FDIM + i];
    for (int i = t; i < PCN * FDIM; i += 256) xp[i] = x_pc[b * PCN * FDIM + i];
    for (int i = t; i < FDIM * HDIM; i += 256) { wi1[i] = W_in_sq[i]; wi2[i] = W_in_pc[i]; }
    __syncthreads();

    // ---- Phase 1: h = gelu(x @ W_in + b_in) ----
    {
        const int c  = t & 127;
        const int rh = t >> 7;  // 0 or 1
        float wcol[16];
        #pragma unroll
        for (int k = 0; k < 16; k++) wcol[k] = wi1[k * 128 + c];
        float bias = b_in_sq[c];
        for (int r = rh * 32; r < rh * 32 + 32; r++) {
            float acc = bias;
            #pragma unroll
            for (int k = 0; k < 16; k++) acc += xs[r * 16 + k] * wcol[k];
            h_sq[r * 128 + c] = gelu_f(acc);
        }
        #pragma unroll
        for (int k = 0; k < 16; k++) wcol[k] = wi2[k * 128 + c];
        bias = b_in_pc[c];
        for (int r = rh * 12; r < rh * 12 + 12; r++) {
            float acc = bias;
            #pragma unroll
            for (int k = 0; k < 16; k++) acc += xp[r * 16 + k] * wcol[k];
            h_pc[r * 128 + c] = gelu_f(acc);
        }
    }
    __syncthreads();

    // ---- Phase 2: raw edge aggregation (column-owner threads, no atomics) ----
    if (t < 128) {
        const int c = t;
        for (int i = 0; i < E_ADJ; i++) {
            int e = eidx[i]; int s = e & 255; int d = e >> 8;
            rawAdj[d * 128 + c] += h_sq[s * 128 + c];
        }
    } else {
        const int c = t - 128;
        const int* ep = eidx + E_ADJ;
        for (int i = 0; i < E_OCC; i++) {
            int e = ep[i]; int s = e & 255; int d = e >> 8;
            rawOcc[d * 128 + c] += h_pc[s * 128 + c];
        }
        ep += E_OCC;
        for (int i = 0; i < E_ATT; i++) {
            int e = ep[i]; int s = e & 255; int d = e >> 8;
            rawAtt[d * 128 + c] += h_pc[s * 128 + c];
        }
        ep += E_ATT;
        for (int i = 0; i < E_DEF; i++) {
            int e = ep[i]; int s = e & 255; int d = e >> 8;
            rawDef[d * 128 + c] += h_pc[s * 128 + c];
        }
        ep += E_DEF;
        for (int i = 0; i < E_REV; i++) {
            int e = ep[i]; int s = e & 255; int d = e >> 8;
            rawRev[d * 128 + c] += h_sq[s * 128 + c];
        }
    }

    const int c4 = (t & 31) * 4;
    const int rg = t >> 5;  // 0..7
    const int bcol = c4 * 2;  // word offset of column-pair group in interleaved tile

    // ---- Phase 3a: agg_sq matmuls + residual + gelu (h_sq in place), f32x2 ----
    {
        uint64_t C[8][4];
        #pragma unroll
        for (int i = 0; i < 8; i++)
            #pragma unroll
            for (int j = 0; j < 4; j++) C[i][j] = 0ull;

        #pragma unroll
        for (int w = 0; w < 2; w++) {
            __syncthreads();  // wst free / raw complete (w==0), wst consumed (w==1)
            stage_kint(wst, w == 0 ? W_adj : W_occ, 128, 0, t);
            __syncthreads();
            const float* raw = (w == 0) ? rawAdj : rawOcc;
            #pragma unroll 4
            for (int kp = 0; kp < 64; kp++) {
                ulonglong2 b01 = *(const ulonglong2*)&wst[kp * 256 + bcol];
                ulonglong2 b23 = *(const ulonglong2*)&wst[kp * 256 + bcol + 4];
                #pragma unroll
                for (int i = 0; i < 8; i++) {
                    uint64_t a = *(const uint64_t*)&raw[(rg * 8 + i) * 128 + kp * 2];
                    ffma2(C[i][0], a, b01.x);
                    ffma2(C[i][1], a, b01.y);
                    ffma2(C[i][2], a, b23.x);
                    ffma2(C[i][3], a, b23.y);
                }
            }
        }
        #pragma unroll
        for (int i = 0; i < 8; i++) {
            int r = rg * 8 + i;
            #pragma unroll
            for (int j = 0; j < 4; j++) {
                float v = h_sq[r * 128 + c4 + j] + pairsum(C[i][j]);
                h_sq[r * 128 + c4 + j] = gelu_f(v);
            }
        }
    }

    // ---- Phase 3b: agg_pc matmuls + residual + gelu (h_pc), f32x2 ----
    {
        uint64_t C[3][4];
        #pragma unroll
        for (int i = 0; i < 3; i++)
            #pragma unroll
            for (int j = 0; j < 4; j++) C[i][j] = 0ull;

        #pragma unroll
        for (int w = 0; w < 3; w++) {
            __syncthreads();
            stage_kint(wst, w == 0 ? W_att : (w == 1 ? W_def : W_rev), 128, 0, t);
            __syncthreads();
            const float* raw = (w == 0) ? rawAtt : (w == 1 ? rawDef : rawRev);
            #pragma unroll 4
            for (int kp = 0; kp < 64; kp++) {
                ulonglong2 b01 = *(const ulonglong2*)&wst[kp * 256 + bcol];
                ulonglong2 b23 = *(const ulonglong2*)&wst[kp * 256 + bcol + 4];
                #pragma unroll
                for (int i = 0; i < 3; i++) {
                    uint64_t a = *(const uint64_t*)&raw[(rg * 3 + i) * 128 + kp * 2];
                    ffma2(C[i][0], a, b01.x);
                    ffma2(C[i][1], a, b01.y);
                    ffma2(C[i][2], a, b23.x);
                    ffma2(C[i][3], a, b23.y);
                }
            }
        }
        #pragma unroll
        for (int i = 0; i < 3; i++) {
            int r = rg * 3 + i;
            #pragma unroll
            for (int j = 0; j < 4; j++) {
                float v = h_pc[r * 128 + c4 + j] + pairsum(C[i][j]);
                h_pc[r * 128 + c4 + j] = gelu_f(v);
            }
        }
    }

    // ---- Phase 4: out = gelu(h2 @ W_out + b_out); board-mean into sacc ----
    #pragma unroll
    for (int h = 0; h < 2; h++) {
        __syncthreads();  // h2 complete (h==0) / wst consumed (h==1)
        stage_kint(wst, W_out, 256, h * 128, t);
        __syncthreads();
        // squares: 64 x 128(half), thread tile 8x4
        {
            uint64_t C[8][4];
            #pragma unroll
            for (int i = 0; i < 8; i++)
                #pragma unroll
                for (int j = 0; j < 4; j++) C[i][j] = 0ull;
            #pragma unroll 4
            for (int kp = 0; kp < 64; kp++) {
                ulonglong2 b01 = *(const ulonglong2*)&wst[kp * 256 + bcol];
                ulonglong2 b23 = *(const ulonglong2*)&wst[kp * 256 + bcol + 4];
                #pragma unroll
                for (int i = 0; i < 8; i++) {
                    uint64_t a = *(const uint64_t*)&h_sq[(rg * 8 + i) * 128 + kp * 2];
                    ffma2(C[i][0], a, b01.x);
                    ffma2(C[i][1], a, b01.y);
                    ffma2(C[i][2], a, b23.x);
                    ffma2(C[i][3], a, b23.y);
                }
            }
            #pragma unroll
            for (int j = 0; j < 4; j++) {
                int cg = h * 128 + c4 + j;
                float bo = b_out[cg];
                float s = 0.f;
                #pragma unroll
                for (int i = 0; i < 8; i++) s += gelu_f(pairsum(C[i][j]) + bo);
                atomicAdd(&sacc[cg], s * (1.0f / 64.0f));
            }
        }
        // pieces: 24 x 128(half), thread tile 3x4
        {
            uint64_t C[3][4];
            #pragma unroll
            for (int i = 0; i < 3; i++)
                #pragma unroll
                for (int j = 0; j < 4; j++) C[i][j] = 0ull;
            #pragma unroll 4
            for (int kp = 0; kp < 64; kp++) {
                ulonglong2 b01 = *(const ulonglong2*)&wst[kp * 256 + bcol];
                ulonglong2 b23 = *(const ulonglong2*)&wst[kp * 256 + bcol + 4];
                #pragma unroll
                for (int i = 0; i < 3; i++) {
                    uint64_t a = *(const uint64_t*)&h_pc[(rg * 3 + i) * 128 + kp * 2];
                    ffma2(C[i][0], a, b01.x);
                    ffma2(C[i][1], a, b01.y);
                    ffma2(C[i][2], a, b23.x);
                    ffma2(C[i][3], a, b23.y);
                }
            }
            #pragma unroll
            for (int j = 0; j < 4; j++) {
                int cg = h * 128 + c4 + j;
                float bo = b_out[cg];
                float s = 0.f;
                #pragma unroll
                for (int i = 0; i < 3; i++) s += gelu_f(pairsum(C[i][j]) + bo);
                atomicAdd(&sacc[cg], s * (1.0f / 24.0f));
            }
        }
    }
    __syncthreads();
    g_shared[b * DDIM + t] = sacc[t];
}

// ============================================================================
// Kernel 2: pt = gelu(shared @ W_pt + b_pt), vt = gelu(shared @ W_vt + b_vt)
// ============================================================================
#define SMEM2_BYTES ((4096 + 32768) * 4)
__global__ void __launch_bounds__(256) heads_kernel(
    const float* __restrict__ W_pt, const float* __restrict__ b_pt,
    const float* __restrict__ W_vt, const float* __restrict__ b_vt)
{
    extern __shared__ float sm[];
    float* At = sm;          // 16*256
    float* Bt = sm + 4096;   // 256*128
    const int t = threadIdx.x;
    const int r0 = blockIdx.x * 16;

    for (int i = t; i < 16 * 256; i += 256) At[i] = g_shared[r0 * 256 + i];

    const int c4 = (t & 31) * 4;
    const int rg = t >> 5;

    #pragma unroll
    for (int w = 0; w < 2; w++) {
        __syncthreads();
        const float* W  = w ? W_vt : W_pt;
        const float* bb = w ? b_vt : b_pt;
        float* outp     = w ? g_vt : g_pt;
        for (int i = t; i < 256 * 128; i += 256) Bt[i] = W[i];
        __syncthreads();
        float C[2][4] = {{0.f, 0.f, 0.f, 0.f}, {0.f, 0.f, 0.f, 0.f}};
        #pragma unroll 4
        for (int k = 0; k < 256; k++) {
            float4 bv = *(const float4*)&Bt[k * 128 + c4];
            float a0 = At[(rg * 2) * 256 + k];
            float a1 = At[(rg * 2 + 1) * 256 + k];
            C[0][0] += a0 * bv.x; C[0][1] += a0 * bv.y; C[0][2] += a0 * bv.z; C[0][3] += a0 * bv.w;
            C[1][0] += a1 * bv.x; C[1][1] += a1 * bv.y; C[1][2] += a1 * bv.z; C[1][3] += a1 * bv.w;
        }
        #pragma unroll
        for (int i = 0; i < 2; i++) {
            int r = r0 + rg * 2 + i;
            float4 o;
            o.x = gelu_f(C[i][0] + bb[c4 + 0]);
            o.y = gelu_f(C[i][1] + bb[c4 + 1]);
            o.z = gelu_f(C[i][2] + bb[c4 + 2]);
            o.w = gelu_f(C[i][3] + bb[c4 + 3]);
            *(float4*)&outp[r * 128 + c4] = o;
        }
    }
}

// ============================================================================
// Kernel 3: policy = pt @ W_ph + b_ph  (2048 x 4672, K=128) — f32x2
// ============================================================================
#define SMEM3_BYTES ((8192 + 16384) * 4)
__global__ void __launch_bounds__(256) policy_kernel(
    const float* __restrict__ W_ph, const float* __restrict__ b_ph,
    float* __restrict__ out)
{
    extern __shared__ float sm[];
    float* At = sm;          // 64*128 (row-major)
    float* Bt = sm + 8192;   // 128x128 k-interleaved
    const int t = threadIdx.x;
    const int rb = blockIdx.y * 64;
    const int cb = blockIdx.x * 128;

    for (int i = t; i < 64 * 128; i += 256) At[i] = g_pt[rb * 128 + i];
    // stage B tile k-interleaved with column guard
    #pragma unroll
    for (int it = 0; it < 16; it++) {
        int m = t + it * 256;        // 64 kp x 64 col-pairs
        int kp = m >> 6;
        int c  = (m & 63) * 2;
        int col = cb + c;
        float2 r0 = make_float2(0.f, 0.f), r1 = make_float2(0.f, 0.f);
        if (col < ADIM) {
            r0 = *(const float2*)&W_ph[(2 * kp)     * ADIM + col];
            r1 = *(const float2*)&W_ph[(2 * kp + 1) * ADIM + col];
        }
        float4 o = make_float4(r0.x, r1.x, r0.y, r1.y);
        *(float4*)&Bt[kp * 256 + c * 2] = o;
    }
    __syncthreads();

    const int c4 = (t & 31) * 4;
    const int rg = t >> 5;
    const int bcol = c4 * 2;
    uint64_t C[8][4];
    #pragma unroll
    for (int i = 0; i < 8; i++)
        #pragma unroll
        for (int j = 0; j < 4; j++) C[i][j] = 0ull;

    #pragma unroll 4
    for (int kp = 0; kp < 64; kp++) {
        ulonglong2 b01 = *(const ulonglong2*)&Bt[kp * 256 + bcol];
        ulonglong2 b23 = *(const ulonglong2*)&Bt[kp * 256 + bcol + 4];
        #pragma unroll
        for (int i = 0; i < 8; i++) {
            uint64_t a = *(const uint64_t*)&At[(rg * 8 + i) * 128 + kp * 2];
            ffma2(C[i][0], a, b01.x);
            ffma2(C[i][1], a, b01.y);
            ffma2(C[i][2], a, b23.x);
            ffma2(C[i][3], a, b23.y);
        }
    }
    #pragma unroll
    for (int i = 0; i < 8; i++) {
        int r = rb + rg * 8 + i;
        #pragma unroll
        for (int j = 0; j < 4; j++) {
            int col = cb + c4 + j;
            if (col < ADIM) out[r * ADIM + col] = pairsum(C[i][j]) + b_ph[col];
        }
    }
}

// ============================================================================
// Kernel 4: value = tanh(vt @ W_vh + b_vh)  (2048 x 1)
// ============================================================================
__global__ void __launch_bounds__(256) value_kernel(
    const float* __restrict__ W_vh, const float* __restrict__ b_vh,
    float* __restrict__ out)
{
    int r = blockIdx.x * 8 + (threadIdx.x >> 5);
    int lane = threadIdx.x & 31;
    float acc = 0.f;
    #pragma unroll
    for (int q = 0; q < 4; q++)
        acc += g_vt[r * 128 + q * 32 + lane] * W_vh[q * 32 + lane];
    #pragma unroll
    for (int o = 16; o; o >>= 1) acc += __shfl_xor_sync(0xffffffffu, acc, o);
    if (lane == 0) out[(size_t)NB * ADIM + r] = tanhf(acc + b_vh[0]);
}

// ============================================================================
extern "C" void kernel_launch(void* const* d_in, const int* in_sizes, int n_in,
                              void* d_out, int out_size) {
    (void)in_sizes; (void)n_in; (void)out_size;
    const float* x_sq    = (const float*)d_in[0];
    const float* x_pc    = (const float*)d_in[1];
    const float* W_in_sq = (const float*)d_in[2];
    const float* b_in_sq = (const float*)d_in[3];
    const float* W_in_pc = (const float*)d_in[4];
    const float* b_in_pc = (const float*)d_in[5];
    const float* W_adj   = (const float*)d_in[6];
    const float* W_occ   = (const float*)d_in[7];
    const float* W_att   = (const float*)d_in[8];
    const float* W_def   = (const float*)d_in[9];
    const float* W_rev   = (const float*)d_in[10];
    const float* W_out   = (const float*)d_in[11];
    const float* b_out   = (const float*)d_in[12];
    const float* W_pt    = (const float*)d_in[13];
    const float* b_pt    = (const float*)d_in[14];
    const float* W_vt    = (const float*)d_in[15];
    const float* b_vt    = (const float*)d_in[16];
    const float* W_ph    = (const float*)d_in[17];
    const float* b_ph    = (const float*)d_in[18];
    const float* W_vh    = (const float*)d_in[19];
    const float* b_vh    = (const float*)d_in[20];
    const int* ei_adj    = (const int*)d_in[21];
    const int* ei_occ    = (const int*)d_in[22];
    const int* ei_att    = (const int*)d_in[23];
    const int* ei_def    = (const int*)d_in[24];
    const int* ei_rev    = (const int*)d_in[25];
    float* out = (float*)d_out;

    cudaFuncSetAttribute(board_kernel,  cudaFuncAttributeMaxDynamicSharedMemorySize, SMEM1_BYTES);
    cudaFuncSetAttribute(heads_kernel,  cudaFuncAttributeMaxDynamicSharedMemorySize, SMEM2_BYTES);
    cudaFuncSetAttribute(policy_kernel, cudaFuncAttributeMaxDynamicSharedMemorySize, SMEM3_BYTES);

    board_kernel<<<NB, 256, SMEM1_BYTES>>>(
        x_sq, x_pc, W_in_sq, b_in_sq, W_in_pc, b_in_pc,
        W_adj, W_occ, W_att, W_def, W_rev, W_out, b_out,
        ei_adj, ei_occ, ei_att, ei_def, ei_rev);

    heads_kernel<<<NB / 16, 256, SMEM2_BYTES>>>(W_pt, b_pt, W_vt, b_vt);

    policy_kernel<<<dim3((ADIM + 127) / 128, NB / 64), 256, SMEM3_BYTES>>>(W_ph, b_ph, out);

    value_kernel<<<NB / 8, 256>>>(W_vh, b_vh, out);
}

// round 7
// speedup vs baseline: 1.1830x; 1.1830x over previous
#include <cuda_runtime.h>
#include <math.h>
#include <stdint.h>

// ---------------- problem constants ----------------
#define NB   2048
#define SQN  64
#define PCN  24
#define FDIM 16
#define HDIM 128
#define DDIM 256
#define TDIM 128
#define ADIM 4672
#define E_ADJ 420
#define E_OCC 24
#define E_ATT 40
#define E_DEF 40
#define E_REV 24
#define T512 512

// ---------------- scratch (static device globals: allocation-free) ----------------
__device__ float g_shared[NB * DDIM];  // 2 MB
__device__ float g_pt[NB * TDIM];      // 1 MB
__device__ float g_vt[NB * TDIM];      // 1 MB

// gelu via __expf (MUFU.EX2); rel err ~1e-6, far under 1e-3 budget.
__device__ __forceinline__ float gelu_f(float x) {
    float u = 0.7978845608028654f * x + 0.0356774081f * x * x * x;
    float au = fabsf(u);
    float e = __expf(-2.0f * au);
    float t = __fdividef(1.0f - e, 1.0f + e);
    t = copysignf(t, u);
    return 0.5f * x * (1.0f + t);
}

// ---------------- smem layout for board kernel (word offsets) ----------------
#define OFF_HSQ   0        // 64*128  = 8192
#define OFF_HPC   8192     // 24*128  = 3072
#define OFF_RADJ  11264    // 64*128  = 8192
#define OFF_AGGO  19456    // 64*128  = 8192
#define OFF_RATT  27648    // 24*128  = 3072
#define OFF_RDEF  30720    // 24*128  = 3072
#define OFF_RREV  33792    // 24*128  = 3072
#define OFF_POCC  36864    // 24*128  = 3072
#define OFF_WST   39936    // 128*128 = 16384
#define OFF_SACC  56320    // 256
#define OFF_EIDX  56576    // 548 ints
#define SMEM1_BYTES (56576*4 + 548*4)   // 228496 B

// ---- weight prefetch helpers: 16384-float tile, 512 threads, 8 float4 each ----
__device__ __forceinline__ void pf_load128(float4* pf, const float* W, int t) {
    const float4* W4 = (const float4*)W;
    #pragma unroll
    for (int i = 0; i < 8; i++) pf[i] = W4[t + i * T512];
}
// W_out is (128,256); load half hh (cols hh*128..+128) into 128x128 tile regs
__device__ __forceinline__ void pf_load_out(float4* pf, const float* W_out, int hh, int t) {
    const float4* W4 = (const float4*)W_out;
    #pragma unroll
    for (int i = 0; i < 8; i++) {
        int idx = t + i * T512;     // 0..4095 float4 of the 128x128 tile
        int k = idx >> 5;           // row
        int c = idx & 31;           // float4-col within half
        pf[i] = W4[k * 64 + hh * 32 + c];
    }
}
__device__ __forceinline__ void pf_store(float* wst, const float4* pf, int t) {
    float4* w4 = (float4*)wst;
    #pragma unroll
    for (int i = 0; i < 8; i++) w4[t + i * T512] = pf[i];
}

// ---- register-tiled GEMM fragments ----
// 64-row A (64x128) @ wst (128x128): thread tile 4 rows x 4 cols
__device__ __forceinline__ void gemm64(const float* __restrict__ A,
                                       const float* __restrict__ wst,
                                       float C[4][4], int rg, int c4) {
    #pragma unroll 4
    for (int k = 0; k < 128; k++) {
        float4 bv = *(const float4*)&wst[k * 128 + c4];
        #pragma unroll
        for (int i = 0; i < 4; i++) {
            float a = A[(rg * 4 + i) * 128 + k];
            C[i][0] += a * bv.x; C[i][1] += a * bv.y;
            C[i][2] += a * bv.z; C[i][3] += a * bv.w;
        }
    }
}
// 24-row A (24x128) @ wst (128x128): thread tile 3 rows x 2 cols
__device__ __forceinline__ void gemm24(const float* __restrict__ A,
                                       const float* __restrict__ wst,
                                       float C[3][2], int rg2, int c2) {
    #pragma unroll 4
    for (int k = 0; k < 128; k++) {
        float2 bv = *(const float2*)&wst[k * 128 + c2];
        #pragma unroll
        for (int i = 0; i < 3; i++) {
            float a = A[(rg2 * 3 + i) * 128 + k];
            C[i][0] += a * bv.x; C[i][1] += a * bv.y;
        }
    }
}

// ============================================================================
// Kernel 1: one CTA (512 thr) per board. Fully fused GNN -> g_shared[b][256].
// ============================================================================
__global__ void __launch_bounds__(T512, 1) board_kernel(
    const float* __restrict__ x_sq, const float* __restrict__ x_pc,
    const float* __restrict__ W_in_sq, const float* __restrict__ b_in_sq,
    const float* __restrict__ W_in_pc, const float* __restrict__ b_in_pc,
    const float* __restrict__ W_adj, const float* __restrict__ W_occ,
    const float* __restrict__ W_att, const float* __restrict__ W_def,
    const float* __restrict__ W_rev,
    const float* __restrict__ W_out, const float* __restrict__ b_out,
    const int* __restrict__ ei_adj, const int* __restrict__ ei_occ,
    const int* __restrict__ ei_att, const int* __restrict__ ei_def,
    const int* __restrict__ ei_rev)
{
    extern __shared__ float sm[];
    float* h_sq   = sm + OFF_HSQ;
    float* h_pc   = sm + OFF_HPC;
    float* rawAdj = sm + OFF_RADJ;
    float* aggO   = sm + OFF_AGGO;
    float* rawAtt = sm + OFF_RATT;
    float* rawDef = sm + OFF_RDEF;
    float* rawRev = sm + OFF_RREV;
    float* p_occ  = sm + OFF_POCC;
    float* wst    = sm + OFF_WST;
    float* sacc   = sm + OFF_SACC;
    int*   eidx   = (int*)(sm + OFF_EIDX);

    const int b = blockIdx.x;
    const int t = threadIdx.x;

    float4 pf[8];
    pf_load128(pf, W_adj, t);   // prefetch first weight tile immediately

    // ---- load edges, board-local, pack s | d<<8.
    // layout: adj[0,420) att[420,460) def[460,500) rev[500,524) occ[524,548)
    {
        const int ba = b * E_ADJ;
        for (int i = t; i < E_ADJ; i += T512) {
            int s = ei_adj[ba + i] - b * SQN;
            int d = ei_adj[NB * E_ADJ + ba + i] - b * SQN;
            eidx[i] = s | (d << 8);
        }
        const int bt = b * E_ATT;
        for (int i = t; i < E_ATT; i += T512) {
            int s  = ei_att[bt + i] - b * PCN;
            int d  = ei_att[NB * E_ATT + bt + i] - b * PCN;
            eidx[E_ADJ + i] = s | (d << 8);
            int s2 = ei_def[bt + i] - b * PCN;
            int d2 = ei_def[NB * E_DEF + bt + i] - b * PCN;
            eidx[E_ADJ + E_ATT + i] = s2 | (d2 << 8);
        }
        const int bo = b * E_OCC;
        for (int i = t; i < E_REV; i += T512) {
            int s = ei_rev[bo + i] - b * SQN;                  // src: square
            int d = ei_rev[NB * E_REV + bo + i] - b * PCN;     // dst: piece
            eidx[500 + i] = s | (d << 8);
            int so = ei_occ[bo + i] - b * PCN;                 // src: piece
            int dd = ei_occ[NB * E_OCC + bo + i] - b * SQN;    // dst: square
            eidx[524 + i] = so | (dd << 8);
        }
    }

    // ---- zero raw buffers (rawAdj..rawRev contiguous, 25600 words) + sacc ----
    {
        float4* r4 = (float4*)rawAdj;
        for (int i = t; i < 6400; i += T512) r4[i] = make_float4(0.f, 0.f, 0.f, 0.f);
        if (t < 256) sacc[t] = 0.f;
    }

    // ---- stage x tiles + input weights into wst (plain layout) ----
    float* xs  = wst;              // 64*16
    float* xp  = wst + 1024;       // 24*16
    float* wi1 = wst + 2048;       // 16*128
    float* wi2 = wst + 4096;       // 16*128
    for (int i = t; i < SQN * FDIM; i += T512) xs[i] = x_sq[b * SQN * FDIM + i];
    for (int i = t; i < PCN * FDIM; i += T512) xp[i] = x_pc[b * PCN * FDIM + i];
    for (int i = t; i < FDIM * HDIM; i += T512) { wi1[i] = W_in_sq[i]; wi2[i] = W_in_pc[i]; }
    __syncthreads();   // S1

    // ---- Phase 1: h = gelu(x @ W_in + b_in). 512 thr: c = t&127, q = t>>7 ----
    {
        const int c = t & 127;
        const int q = t >> 7;  // 0..3
        float wcol[16];
        #pragma unroll
        for (int k = 0; k < 16; k++) wcol[k] = wi1[k * 128 + c];
        float bias = b_in_sq[c];
        for (int r = q * 16; r < q * 16 + 16; r++) {
            float acc = bias;
            #pragma unroll
            for (int k = 0; k < 16; k++) acc += xs[r * 16 + k] * wcol[k];
            h_sq[r * 128 + c] = gelu_f(acc);
        }
        #pragma unroll
        for (int k = 0; k < 16; k++) wcol[k] = wi2[k * 128 + c];
        bias = b_in_pc[c];
        for (int r = q * 6; r < q * 6 + 6; r++) {
            float acc = bias;
            #pragma unroll
            for (int k = 0; k < 16; k++) acc += xp[r * 16 + k] * wcol[k];
            h_pc[r * 128 + c] = gelu_f(acc);
        }
    }
    __syncthreads();   // S2

    // ---- Phase 2: edge aggregation via smem atomics (fire-and-forget) ----
    {
        const int g = t >> 7;     // 0..3 edge-strided groups
        const int c = t & 127;
        for (int i = g; i < E_ADJ; i += 4) {
            int e = eidx[i];
            atomicAdd(&rawAdj[(e >> 8) * 128 + c], h_sq[(e & 255) * 128 + c]);
        }
        for (int i = g; i < E_ATT; i += 4) {
            int e = eidx[E_ADJ + i];
            atomicAdd(&rawAtt[(e >> 8) * 128 + c], h_pc[(e & 255) * 128 + c]);
        }
        for (int i = g; i < E_DEF; i += 4) {
            int e = eidx[E_ADJ + E_ATT + i];
            atomicAdd(&rawDef[(e >> 8) * 128 + c], h_pc[(e & 255) * 128 + c]);
        }
        for (int i = g; i < E_REV; i += 4) {
            int e = eidx[500 + i];
            atomicAdd(&rawRev[(e >> 8) * 128 + c], h_sq[(e & 255) * 128 + c]);
        }
    }
    __syncthreads();   // S3 (raw done; wst free)

    const int c4  = (t & 31) * 4;
    const int rg  = t >> 5;   // 0..15 (4-row groups)
    const int c2  = (t & 63) * 2;
    const int rg2 = t >> 6;   // 0..7 (3-row groups)

    pf_store(wst, pf, t);            // W_adj -> wst
    pf_load128(pf, W_occ, t);        // prefetch W_occ (overlaps next GEMM)
    __syncthreads();   // S4

    // ---- GEMM adj: C_adj = rawAdj @ W_adj ----
    float Cadj[4][4];
    #pragma unroll
    for (int i = 0; i < 4; i++)
        #pragma unroll
        for (int j = 0; j < 4; j++) Cadj[i][j] = 0.f;
    gemm64(rawAdj, wst, Cadj, rg, c4);
    __syncthreads();   // S5 (wst consumed)

    pf_store(wst, pf, t);            // W_occ
    pf_load128(pf, W_att, t);
    __syncthreads();   // S6

    // ---- GEMM occ (24 rows): p_occ = h_pc @ W_occ ----
    {
        float C[3][2] = {{0.f,0.f},{0.f,0.f},{0.f,0.f}};
        gemm24(h_pc, wst, C, rg2, c2);
        #pragma unroll
        for (int i = 0; i < 3; i++) {
            p_occ[(rg2 * 3 + i) * 128 + c2]     = C[i][0];
            p_occ[(rg2 * 3 + i) * 128 + c2 + 1] = C[i][1];
        }
    }
    __syncthreads();   // S7 (p_occ visible; wst consumed)

    pf_store(wst, pf, t);            // W_att
    pf_load128(pf, W_def, t);
    // scatter occ rows into aggO (24 edges, atomics)
    {
        const int g = t >> 7;
        const int c = t & 127;
        for (int i = g; i < E_OCC; i += 4) {
            int e = eidx[524 + i];
            atomicAdd(&aggO[(e >> 8) * 128 + c], p_occ[(e & 255) * 128 + c]);
        }
    }
    __syncthreads();   // S8 (aggO done; W_att ready)

    // ---- epilogue squares: h_sq = gelu(h_sq + C_adj + aggO) ----
    #pragma unroll
    for (int i = 0; i < 4; i++) {
        int r = rg * 4 + i;
        #pragma unroll
        for (int j = 0; j < 4; j++) {
            float v = h_sq[r * 128 + c4 + j] + Cadj[i][j] + aggO[r * 128 + c4 + j];
            h_sq[r * 128 + c4 + j] = gelu_f(v);
        }
    }

    // ---- piece GEMM chain: C_pc = rawAtt@W_att + rawDef@W_def + rawRev@W_rev ----
    float Cpc[3][2] = {{0.f,0.f},{0.f,0.f},{0.f,0.f}};
    gemm24(rawAtt, wst, Cpc, rg2, c2);
    __syncthreads();   // S9
    pf_store(wst, pf, t);            // W_def
    pf_load128(pf, W_rev, t);
    __syncthreads();   // S10
    gemm24(rawDef, wst, Cpc, rg2, c2);
    __syncthreads();   // S11
    pf_store(wst, pf, t);            // W_rev
    pf_load_out(pf, W_out, 0, t);    // prefetch W_out half0
    __syncthreads();   // S12
    gemm24(rawRev, wst, Cpc, rg2, c2);
    // epilogue pieces: h_pc = gelu(h_pc + C_pc)
    #pragma unroll
    for (int i = 0; i < 3; i++) {
        int r = rg2 * 3 + i;
        #pragma unroll
        for (int j = 0; j < 2; j++) {
            float v = h_pc[r * 128 + c2 + j] + Cpc[i][j];
            h_pc[r * 128 + c2 + j] = gelu_f(v);
        }
    }
    __syncthreads();   // S13 (h_sq/h_pc final; wst consumed)

    // ---- Phase 4: out = gelu(h2 @ W_out + b_out); board-mean into sacc ----
    #pragma unroll
    for (int hh = 0; hh < 2; hh++) {
        pf_store(wst, pf, t);        // W_out half hh
        if (hh == 0) pf_load_out(pf, W_out, 1, t);
        __syncthreads();
        // squares 64 rows
        {
            float C[4][4];
            #pragma unroll
            for (int i = 0; i < 4; i++)
                #pragma unroll
                for (int j = 0; j < 4; j++) C[i][j] = 0.f;
            gemm64(h_sq, wst, C, rg, c4);
            #pragma unroll
            for (int j = 0; j < 4; j++) {
                int cg = hh * 128 + c4 + j;
                float bo = b_out[cg];
                float s = 0.f;
                #pragma unroll
                for (int i = 0; i < 4; i++) s += gelu_f(C[i][j] + bo);
                atomicAdd(&sacc[cg], s * (1.0f / 64.0f));
            }
        }
        // pieces 24 rows
        {
            float C[3][2] = {{0.f,0.f},{0.f,0.f},{0.f,0.f}};
            gemm24(h_pc, wst, C, rg2, c2);
            #pragma unroll
            for (int j = 0; j < 2; j++) {
                int cg = hh * 128 + c2 + j;
                float bo = b_out[cg];
                float s = 0.f;
                #pragma unroll
                for (int i = 0; i < 3; i++) s += gelu_f(C[i][j] + bo);
                atomicAdd(&sacc[cg], s * (1.0f / 24.0f));
            }
        }
        __syncthreads();
    }
    if (t < 256) g_shared[b * DDIM + t] = sacc[t];
}

// ============================================================================
// Kernel 2: pt = gelu(shared @ W_pt + b_pt), vt = gelu(shared @ W_vt + b_vt)
// ============================================================================
#define SMEM2_BYTES ((4096 + 32768) * 4)
__global__ void __launch_bounds__(256) heads_kernel(
    const float* __restrict__ W_pt, const float* __restrict__ b_pt,
    const float* __restrict__ W_vt, const float* __restrict__ b_vt)
{
    extern __shared__ float sm[];
    float* At = sm;          // 16*256
    float* Bt = sm + 4096;   // 256*128
    const int t = threadIdx.x;
    const int r0 = blockIdx.x * 16;

    for (int i = t; i < 16 * 256; i += 256) At[i] = g_shared[r0 * 256 + i];

    const int c4 = (t & 31) * 4;
    const int rg = t >> 5;

    #pragma unroll
    for (int w = 0; w < 2; w++) {
        __syncthreads();
        const float* W  = w ? W_vt : W_pt;
        const float* bb = w ? b_vt : b_pt;
        float* outp     = w ? g_vt : g_pt;
        for (int i = t; i < 256 * 128; i += 256) Bt[i] = W[i];
        __syncthreads();
        float C[2][4] = {{0.f, 0.f, 0.f, 0.f}, {0.f, 0.f, 0.f, 0.f}};
        #pragma unroll 4
        for (int k = 0; k < 256; k++) {
            float4 bv = *(const float4*)&Bt[k * 128 + c4];
            float a0 = At[(rg * 2) * 256 + k];
            float a1 = At[(rg * 2 + 1) * 256 + k];
            C[0][0] += a0 * bv.x; C[0][1] += a0 * bv.y; C[0][2] += a0 * bv.z; C[0][3] += a0 * bv.w;
            C[1][0] += a1 * bv.x; C[1][1] += a1 * bv.y; C[1][2] += a1 * bv.z; C[1][3] += a1 * bv.w;
        }
        #pragma unroll
        for (int i = 0; i < 2; i++) {
            int r = r0 + rg * 2 + i;
            float4 o;
            o.x = gelu_f(C[i][0] + bb[c4 + 0]);
            o.y = gelu_f(C[i][1] + bb[c4 + 1]);
            o.z = gelu_f(C[i][2] + bb[c4 + 2]);
            o.w = gelu_f(C[i][3] + bb[c4 + 3]);
            *(float4*)&outp[r * 128 + c4] = o;
        }
    }
}

// ============================================================================
// Kernel 3: policy = pt @ W_ph + b_ph  (2048 x 4672, K=128)
// ============================================================================
#define SMEM3_BYTES ((8192 + 16384) * 4)
__global__ void __launch_bounds__(256) policy_kernel(
    const float* __restrict__ W_ph, const float* __restrict__ b_ph,
    float* __restrict__ out)
{
    extern __shared__ float sm[];
    float* At = sm;          // 64*128
    float* Bt = sm + 8192;   // 128*128
    const int t = threadIdx.x;
    const int rb = blockIdx.y * 64;
    const int cb = blockIdx.x * 128;

    for (int i = t; i < 64 * 128; i += 256) At[i] = g_pt[rb * 128 + i];
    for (int m = t; m < 128 * 128; m += 256) {
        int k = m >> 7, j = m & 127;
        int col = cb + j;
        Bt[m] = (col < ADIM) ? W_ph[k * ADIM + col] : 0.f;
    }
    __syncthreads();

    const int c4 = (t & 31) * 4;
    const int rg = t >> 5;
    float C[8][4];
    #pragma unroll
    for (int i = 0; i < 8; i++)
        #pragma unroll
        for (int j = 0; j < 4; j++) C[i][j] = 0.f;

    #pragma unroll 4
    for (int k = 0; k < 128; k++) {
        float4 bv = *(const float4*)&Bt[k * 128 + c4];
        #pragma unroll
        for (int i = 0; i < 8; i++) {
            float a = At[(rg * 8 + i) * 128 + k];
            C[i][0] += a * bv.x; C[i][1] += a * bv.y;
            C[i][2] += a * bv.z; C[i][3] += a * bv.w;
        }
    }
    #pragma unroll
    for (int i = 0; i < 8; i++) {
        int r = rb + rg * 8 + i;
        #pragma unroll
        for (int j = 0; j < 4; j++) {
            int col = cb + c4 + j;
            if (col < ADIM) out[r * ADIM + col] = C[i][j] + b_ph[col];
        }
    }
}

// ============================================================================
// Kernel 4: value = tanh(vt @ W_vh + b_vh)  (2048 x 1)
// ============================================================================
__global__ void __launch_bounds__(256) value_kernel(
    const float* __restrict__ W_vh, const float* __restrict__ b_vh,
    float* __restrict__ out)
{
    int r = blockIdx.x * 8 + (threadIdx.x >> 5);
    int lane = threadIdx.x & 31;
    float acc = 0.f;
    #pragma unroll
    for (int q = 0; q < 4; q++)
        acc += g_vt[r * 128 + q * 32 + lane] * W_vh[q * 32 + lane];
    #pragma unroll
    for (int o = 16; o; o >>= 1) acc += __shfl_xor_sync(0xffffffffu, acc, o);
    if (lane == 0) out[(size_t)NB * ADIM + r] = tanhf(acc + b_vh[0]);
}

// ============================================================================
extern "C" void kernel_launch(void* const* d_in, const int* in_sizes, int n_in,
                              void* d_out, int out_size) {
    (void)in_sizes; (void)n_in; (void)out_size;
    const float* x_sq    = (const float*)d_in[0];
    const float* x_pc    = (const float*)d_in[1];
    const float* W_in_sq = (const float*)d_in[2];
    const float* b_in_sq = (const float*)d_in[3];
    const float* W_in_pc = (const float*)d_in[4];
    const float* b_in_pc = (const float*)d_in[5];
    const float* W_adj   = (const float*)d_in[6];
    const float* W_occ   = (const float*)d_in[7];
    const float* W_att   = (const float*)d_in[8];
    const float* W_def   = (const float*)d_in[9];
    const float* W_rev   = (const float*)d_in[10];
    const float* W_out   = (const float*)d_in[11];
    const float* b_out   = (const float*)d_in[12];
    const float* W_pt    = (const float*)d_in[13];
    const float* b_pt    = (const float*)d_in[14];
    const float* W_vt    = (const float*)d_in[15];
    const float* b_vt    = (const float*)d_in[16];
    const float* W_ph    = (const float*)d_in[17];
    const float* b_ph    = (const float*)d_in[18];
    const float* W_vh    = (const float*)d_in[19];
    const float* b_vh    = (const float*)d_in[20];
    const int* ei_adj    = (const int*)d_in[21];
    const int* ei_occ    = (const int*)d_in[22];
    const int* ei_att    = (const int*)d_in[23];
    const int* ei_def    = (const int*)d_in[24];
    const int* ei_rev    = (const int*)d_in[25];
    float* out = (float*)d_out;

    cudaFuncSetAttribute(board_kernel,  cudaFuncAttributeMaxDynamicSharedMemorySize, SMEM1_BYTES);
    cudaFuncSetAttribute(heads_kernel,  cudaFuncAttributeMaxDynamicSharedMemorySize, SMEM2_BYTES);
    cudaFuncSetAttribute(policy_kernel, cudaFuncAttributeMaxDynamicSharedMemorySize, SMEM3_BYTES);

    board_kernel<<<NB, T512, SMEM1_BYTES>>>(
        x_sq, x_pc, W_in_sq, b_in_sq, W_in_pc, b_in_pc,
        W_adj, W_occ, W_att, W_def, W_rev, W_out, b_out,
        ei_adj, ei_occ, ei_att, ei_def, ei_rev);

    heads_kernel<<<NB / 16, 256, SMEM2_BYTES>>>(W_pt, b_pt, W_vt, b_vt);

    policy_kernel<<<dim3((ADIM + 127) / 128, NB / 64), 256, SMEM3_BYTES>>>(W_ph, b_ph, out);

    value_kernel<<<NB / 8, 256>>>(W_vh, b_vh, out);
}